// round 9
// baseline (speedup 1.0000x reference)
#include <cuda_runtime.h>
#include <cstdint>

#define SA 20        // alphabet
#define HH 2
#define KK 2
#define NM 4         // H*K matrices
#define LL 512
#define BB 1024
#define NRATES 100000
#define NSWEEP 5
#define PPB 512      // positions per fused block
#define NBLK (BB * LL * HH / PPB)   // 2048 fused blocks

// persistent scratch (allocation-free rule: __device__ globals)
__device__ float g_U[NM][SA][SA];
__device__ float g_lam[NM][SA];
__device__ float g_sp[NM][SA];
__device__ float g_isp[NM][SA];
__device__ int   g_flag;

__device__ __forceinline__ float softplusf(float x) {
    return fmaxf(x, 0.f) + log1pf(expf(-fabsf(x)));
}

__global__ void reset_kernel() { g_flag = 0; }

// ---------------- Fused kernel ----------------
// Blocks 0..NM-1: Jacobi eigensolve -> globals -> flag.
// Blocks NM..:    scan own 512 positions (overlaps eig), wait flag,
//                 build P in smem, stream coalesced output.
__global__ __launch_bounds__(512)
void fused_kernel(const float* __restrict__ exch, const float* __restrict__ equil,
                  const float* __restrict__ inputs, const int* __restrict__ ridx,
                  const float* __restrict__ tauk, float* __restrict__ out) {
    const int t = threadIdx.x;

    if (blockIdx.x < NM) {
        // ================= eig path =================
        __shared__ float Abuf[2][SA][SA + 1];
        __shared__ float Ubuf[2][SA][SA + 1];
        __shared__ __align__(16) float4 tab[SA];
        __shared__ float pvec[SA], spv[SA], ispv[SA], rowv[SA];
        __shared__ float inv_mue;

        const int m = blockIdx.x;
        const int i = t / SA, j = t % SA;
        const bool act = (t < SA * SA);

        if (t == 0) {
            float mx = -1e30f;
            for (int s = 0; s < SA; s++) mx = fmaxf(mx, equil[m * SA + s]);
            float e[SA], sum = 0.f;
            for (int s = 0; s < SA; s++) { e[s] = expf(equil[m * SA + s] - mx); sum += e[s]; }
            float inv = 1.f / sum;
            for (int s = 0; s < SA; s++) {
                float ps = e[s] * inv;
                pvec[s] = ps;
                float sq = sqrtf(ps);
                spv[s] = sq;
                ispv[s] = 1.f / sq;
            }
        }
        __syncthreads();

        if (act) {
            float kij = exch[m * SA * SA + i * SA + j];
            float kji = exch[m * SA * SA + j * SA + i];
            float rr = (i == j) ? 0.f : softplusf(0.5f * (kij + kji));
            Abuf[0][i][j] = rr * pvec[j];
        }
        __syncthreads();
        if (t < SA) { float s = 0.f; for (int jj = 0; jj < SA; jj++) s += Abuf[0][t][jj]; rowv[t] = s; }
        __syncthreads();
        if (t == 0) {
            float mue = 0.f;
            for (int ii = 0; ii < SA; ii++) mue += pvec[ii] * rowv[ii];
            inv_mue = 1.f / fmaxf(mue, 1e-16f);
        }
        __syncthreads();
        if (act) {
            float q = (Abuf[0][i][j] - ((i == j) ? rowv[i] : 0.f)) * inv_mue;
            Abuf[1][i][j] = spv[i] * q * ispv[j];
        }
        __syncthreads();

        float a = 0.f, u = 0.f;
        if (act) {
            a = 0.5f * (Abuf[1][i][j] + Abuf[1][j][i]);
            u = (i == j) ? 1.f : 0.f;
        }

        for (int round = 0; round < NSWEEP * (SA - 1); round++) {
            const int p = round & 1;
            const int r = round % (SA - 1);
            if (act) { Abuf[p][i][j] = a; Ubuf[p][i][j] = u; }
            __syncthreads();
            if (t < SA / 2) {
                int k = t;
                int posa = k, posb = SA - 1 - k;
                int P_ = (posa == 0) ? 0 : 1 + (posa - 1 + r) % (SA - 1);
                int Q_ = 1 + (posb - 1 + r) % (SA - 1);
                float app = Abuf[p][P_][P_], aqq = Abuf[p][Q_][Q_], apq = Abuf[p][P_][Q_];
                float c = 1.f, s = 0.f;
                if (fabsf(apq) > 1e-13f) {
                    float theta = (aqq - app) / (2.f * apq);
                    float tt = copysignf(1.f, theta) / (fabsf(theta) + sqrtf(theta * theta + 1.f));
                    c = rsqrtf(tt * tt + 1.f);
                    s = tt * c;
                }
                tab[P_] = make_float4(c, -s, (float)Q_, 0.f);
                tab[Q_] = make_float4(c,  s, (float)P_, 0.f);
            }
            __syncthreads();
            if (act) {
                float4 ti = tab[i], tj = tab[j];
                int pi = (int)ti.z, pj = (int)tj.z;
                float ci = ti.x, si = ti.y;
                float cj = tj.x, sj = tj.y;
                float a01 = Abuf[p][i][pj];
                float a10 = Abuf[p][pi][j];
                float a11 = Abuf[p][pi][pj];
                float u1  = Ubuf[p][i][pj];
                a = ci * (cj * a + sj * a01) + si * (cj * a10 + sj * a11);
                u = cj * u + sj * u1;
            }
        }

        if (act) {
            g_U[m][i][j] = u;
            if (i == j) g_lam[m][i] = a;
        }
        if (t < SA) {
            g_sp[m][t]  = spv[t];
            g_isp[m][t] = ispv[t];
        }
        __threadfence();
        __syncthreads();
        if (t == 0) atomicAdd(&g_flag, 1);
        return;
    }

    // ================= fused scan + write path =================
    __shared__ int   zsh[PPB];
    __shared__ __align__(16) float Pm[NM * SA * SA];  // [(h*KK+k)*400 + z*20 + s]
    __shared__ __align__(16) float Us[NM][SA][SA];
    __shared__ __align__(16) float Vs[NM][SA][SA];
    __shared__ float w[NM][SA];
    __shared__ float sps[NM][SA], isps[NM][SA];
    __shared__ float tau[HH];

    const int blk = blockIdx.x - NM;          // 0..NBLK-1
    const int b = blk >> 1;                   // 2 blocks per batch item
    const int posbase = blk * PPB;

    // ---- Phase 1: scan own one-hot slice (independent of eig) ----
    const float4* ip = (const float4*)(inputs + (size_t)posbase * SA);  // 2560 float4
    {
        int p = t / 5;               // e0 = 4t ; p = e0/20
        int r = 4 * t - 20 * p;      // e0 % 20
        for (int i = 0; i < 5; i++) {
            float4 v = ip[t + i * 512];
            int rr, pp;
            rr = r;     pp = p;     if (rr >= 20) { rr -= 20; pp += 1; }
            if (v.x > 0.5f) zsh[pp] = rr;
            rr = r + 1; pp = p;     if (rr >= 20) { rr -= 20; pp += 1; }
            if (v.y > 0.5f) zsh[pp] = rr;
            rr = r + 2; pp = p;     if (rr >= 20) { rr -= 20; pp += 1; }
            if (v.z > 0.5f) zsh[pp] = rr;
            rr = r + 3; pp = p;     if (rr >= 20) { rr -= 20; pp += 1; }
            if (v.w > 0.5f) zsh[pp] = rr;
            // advance by 2048 elements = 102*20 + 8
            p += 102; r += 8; if (r >= 20) { r -= 20; p += 1; }
        }
    }
    if (t < HH) {
        int idx = ridx[b * HH + t];
        tau[t] = softplusf(tauk[t * NRATES + idx]);
    }

    // ---- Wait for eig producers (plain volatile poll: no L2-atomic storm) ----
    if (t == 0) {
        volatile int* vf = &g_flag;
        while (*vf < NM) { __nanosleep(128); }
    }
    __syncthreads();
    __threadfence();

    // ---- Phase 2: build P in smem ----
    if (t < NM * SA) {
        int m = t / SA, s = t % SA;
        int h = m / KK;
        w[m][s]    = expf(tau[h] * g_lam[m][s]);
        sps[m][s]  = g_sp[m][s];
        isps[m][s] = g_isp[m][s];
    }
    __syncthreads();
    for (int e = t; e < NM * SA * SA; e += 512) {
        int m = e / (SA * SA);
        int rs = e % (SA * SA);
        int j = rs / SA, s = rs % SA;
        float uu = g_U[m][j][s];
        Us[m][j][s] = uu;
        Vs[m][j][s] = uu * w[m][s];
    }
    __syncthreads();
    for (int e = t; e < NM * SA * SA; e += 512) {
        int m = e / (SA * SA);
        int rs = e % (SA * SA);
        int i = rs / SA, j = rs % SA;
        float acc = 0.f;
#pragma unroll
        for (int s = 0; s < SA; s++) acc += Us[m][i][s] * Vs[m][j][s];
        Pm[m * SA * SA + i * SA + j] = isps[m][i] * acc * sps[m][j];
    }
    __syncthreads();

    // ---- Phase 3: coalesced write stream (5120 float4s per block) ----
    float4* op = (float4*)(out + (size_t)posbase * (KK * SA));
    int gp = t / 10;           // position-local of float4 index g = t
    int ge = t - 10 * gp;      // element 0..9 within position
    for (int it = 0; it < 10; it++) {
        int z = zsh[gp];
        int h = gp & 1;                      // posbase multiple of 512 -> parity kept
        int k = (ge >= 5) ? 1 : 0;
        int off = (h * KK + k) * (SA * SA) + z * SA + (ge - 5 * k) * 4;
        float4 v = *(const float4*)&Pm[off];
        op[t + it * 512] = v;
        // advance g by 512 = 51*10 + 2
        gp += 51; ge += 2; if (ge >= 10) { ge -= 10; gp += 1; }
    }
}

extern "C" void kernel_launch(void* const* d_in, const int* in_sizes, int n_in,
                              void* d_out, int out_size) {
    const float* inputs = (const float*)d_in[0];   // (B,L,H,20) f32
    const int*   ridx   = (const int*)d_in[1];     // (B,H) i32
    const float* tauk   = (const float*)d_in[2];   // (H,NUM_RATES) f32
    const float* exch   = (const float*)d_in[3];   // (H,K,20,20) f32
    const float* equil  = (const float*)d_in[4];   // (H,K,20) f32
    float* out = (float*)d_out;                    // (B,L,H,K,20) f32

    reset_kernel<<<1, 1>>>();
    fused_kernel<<<NM + NBLK, 512>>>(exch, equil, inputs, ridx, tauk, out);
}

// round 11
// speedup vs baseline: 1.1957x; 1.1957x over previous
#include <cuda_runtime.h>
#include <cstdint>

#define SA 20        // alphabet
#define HH 2
#define KK 2
#define NM 4         // H*K matrices
#define LL 512
#define BB 1024
#define NRATES 100000
#define NSWEEP 5
#define NPOS (BB * LL * HH)      // 1,048,576 positions
#define SCANB 2048               // scan blocks in kernel 1 (512 pos each)
#define PPB2 512                 // positions per anc block
#define BPB2 2                   // anc blocks per batch item

// persistent scratch (allocation-free rule: __device__ globals)
__device__ float   g_U[NM][SA][SA];
__device__ float   g_lam[NM][SA];
__device__ float   g_sp[NM][SA];
__device__ float   g_isp[NM][SA];
__device__ unsigned char g_z[NPOS];   // argmax index per position

__device__ __forceinline__ float softplusf(float x) {
    return fmaxf(x, 0.f) + log1pf(expf(-fabsf(x)));
}

// ---------------- Kernel 1: eig (blocks 0..NM-1) + input scan (rest), concurrent ----------------
__global__ __launch_bounds__(512, 2)
void eig_scan_kernel(const float* __restrict__ exch, const float* __restrict__ equil,
                     const float* __restrict__ inputs) {
    const int t = threadIdx.x;

    if (blockIdx.x >= NM) {
        // ================= scan path: one-hot -> z table =================
        __shared__ int zsh[512];
        const int sb = blockIdx.x - NM;
        const int posbase = sb * 512;                   // 512 positions per block
        const float4* ip = (const float4*)(inputs + (size_t)posbase * SA); // 2560 float4
        int p = t / 5;                 // e0 = 4t ; p = e0/20
        int r = 4 * t - 20 * p;        // e0 % 20
        for (int i = 0; i < 5; i++) {
            float4 v = ip[t + i * 512];
            int rr, pp;
            rr = r;     pp = p;     if (rr >= 20) { rr -= 20; pp += 1; }
            if (v.x > 0.5f) zsh[pp] = rr;
            rr = r + 1; pp = p;     if (rr >= 20) { rr -= 20; pp += 1; }
            if (v.y > 0.5f) zsh[pp] = rr;
            rr = r + 2; pp = p;     if (rr >= 20) { rr -= 20; pp += 1; }
            if (v.z > 0.5f) zsh[pp] = rr;
            rr = r + 3; pp = p;     if (rr >= 20) { rr -= 20; pp += 1; }
            if (v.w > 0.5f) zsh[pp] = rr;
            // advance by 2048 elements = 102*20 + 8
            p += 102; r += 8; if (r >= 20) { r -= 20; p += 1; }
        }
        __syncthreads();
        if (t < 128) {   // pack 4 bytes -> coalesced 512B store
            unsigned int w = (unsigned int)zsh[4 * t]
                           | ((unsigned int)zsh[4 * t + 1] << 8)
                           | ((unsigned int)zsh[4 * t + 2] << 16)
                           | ((unsigned int)zsh[4 * t + 3] << 24);
            ((unsigned int*)(g_z + posbase))[t] = w;
        }
        return;
    }

    // ================= eig path: one barrier/round, replicated fast pivots =================
    __shared__ float Abuf[2][SA][SA + 1];
    __shared__ float Ubuf[2][SA][SA + 1];
    __shared__ int   part[SA - 1][SA];          // partner table per round offset
    __shared__ float pvec[SA], spv[SA], ispv[SA], rowv[SA];
    __shared__ float inv_mue;

    const int m = blockIdx.x;
    const int i = t / SA, j = t % SA;
    const bool act = (t < SA * SA);

    // one-time partner schedule (round-robin tournament, seat 0 fixed)
    if (t < (SA - 1) * SA) {
        int r = t / SA, idx = t % SA;
        int p;
        if (idx == 0) {
            p = 1 + (18 + r) % 19;              // partner of seat 0 = seat 19's index
        } else {
            int s = 1 + ((idx - 1 - r) % 19 + 19) % 19;   // seat of idx
            int ps = 19 - s;
            p = (ps == 0) ? 0 : 1 + (ps - 1 + r) % 19;
        }
        part[r][idx] = p;
    }

    if (t == 0) {
        float mx = -1e30f;
        for (int s = 0; s < SA; s++) mx = fmaxf(mx, equil[m * SA + s]);
        float e[SA], sum = 0.f;
        for (int s = 0; s < SA; s++) { e[s] = expf(equil[m * SA + s] - mx); sum += e[s]; }
        float inv = 1.f / sum;
        for (int s = 0; s < SA; s++) {
            float ps = e[s] * inv;
            pvec[s] = ps;
            float sq = sqrtf(ps);
            spv[s] = sq;
            ispv[s] = 1.f / sq;
        }
    }
    __syncthreads();

    if (act) {
        float kij = exch[m * SA * SA + i * SA + j];
        float kji = exch[m * SA * SA + j * SA + i];
        float rr = (i == j) ? 0.f : softplusf(0.5f * (kij + kji));
        Abuf[0][i][j] = rr * pvec[j];
    }
    __syncthreads();
    if (t < SA) { float s = 0.f; for (int jj = 0; jj < SA; jj++) s += Abuf[0][t][jj]; rowv[t] = s; }
    __syncthreads();
    if (t == 0) {
        float mue = 0.f;
        for (int ii = 0; ii < SA; ii++) mue += pvec[ii] * rowv[ii];
        inv_mue = 1.f / fmaxf(mue, 1e-16f);
    }
    __syncthreads();
    if (act) {
        float q = (Abuf[0][i][j] - ((i == j) ? rowv[i] : 0.f)) * inv_mue;
        Abuf[1][i][j] = spv[i] * q * ispv[j];
    }
    __syncthreads();

    float a = 0.f, u = 0.f;
    if (act) {
        a = 0.5f * (Abuf[1][i][j] + Abuf[1][j][i]);   // symmetric Sm element
        u = (i == j) ? 1.f : 0.f;
    }

    for (int round = 0; round < NSWEEP * (SA - 1); round++) {
        const int p = round & 1;
        const int r = round % (SA - 1);
        if (act) { Abuf[p][i][j] = a; Ubuf[p][i][j] = u; }
        __syncthreads();
        if (act) {
            const int pi = part[r][i], pj = part[r][j];
            // pivot for pair containing i (role P := i) -> ci, si = -s_i
            float aii = Abuf[p][i][i], app_i = Abuf[p][pi][pi], aipi = Abuf[p][i][pi];
            float ci = 1.f, si = 0.f;
            if (fabsf(aipi) > 1e-13f) {
                float th = __fdividef(app_i - aii, 2.f * aipi);
                float t2 = th * th + 1.f;
                float den = fabsf(th) + t2 * rsqrtf(t2);        // |th| + sqrt(th^2+1)
                float tt = __fdividef(copysignf(1.f, th), den);
                ci = rsqrtf(tt * tt + 1.f);
                si = -tt * ci;
            }
            // pivot for pair containing j (role P := j) -> cj, sj = -s_j
            float ajj = Abuf[p][j][j], app_j = Abuf[p][pj][pj], ajpj = Abuf[p][j][pj];
            float cj = 1.f, sj = 0.f;
            if (fabsf(ajpj) > 1e-13f) {
                float th = __fdividef(app_j - ajj, 2.f * ajpj);
                float t2 = th * th + 1.f;
                float den = fabsf(th) + t2 * rsqrtf(t2);
                float tt = __fdividef(copysignf(1.f, th), den);
                cj = rsqrtf(tt * tt + 1.f);
                sj = -tt * cj;
            }
            float a01 = Abuf[p][i][pj];
            float a10 = Abuf[p][pi][j];
            float a11 = Abuf[p][pi][pj];
            float u1  = Ubuf[p][i][pj];
            a = ci * (cj * a + sj * a01) + si * (cj * a10 + sj * a11);
            u = cj * u + sj * u1;
        }
    }

    if (act) {
        g_U[m][i][j] = u;
        if (i == j) g_lam[m][i] = a;
    }
    if (t < SA) {
        g_sp[m][t]  = spv[t];
        g_isp[m][t] = ispv[t];
    }
}

// ---------------- Kernel 2: P reconstruction + pure coalesced write stream ----------------
__global__ __launch_bounds__(256, 8)
void anc_kernel(const int* __restrict__ ridx, const float* __restrict__ tauk,
                float* __restrict__ out) {
    __shared__ __align__(16) float Pm[NM * SA * SA];   // [(h*KK+k)*400 + z*20 + s]
    __shared__ __align__(16) float Us[NM][SA][SA];
    __shared__ __align__(16) float Vs[NM][SA][SA];
    __shared__ float w[NM][SA];
    __shared__ float sps[NM][SA], isps[NM][SA];
    __shared__ float tau[HH];
    __shared__ int   zsh[PPB2];

    const int b = blockIdx.x >> 1;        // BPB2 = 2
    const int q = blockIdx.x & 1;
    const int t = threadIdx.x;
    const int posbase = b * (LL * HH) + q * PPB2;

    // load z slice (512 bytes, coalesced)
    if (t < PPB2 / 4) {
        unsigned int wz = ((const unsigned int*)(g_z + posbase))[t];
        zsh[4 * t]     = wz & 0xff;
        zsh[4 * t + 1] = (wz >> 8) & 0xff;
        zsh[4 * t + 2] = (wz >> 16) & 0xff;
        zsh[4 * t + 3] = (wz >> 24) & 0xff;
    }
    if (t < HH) {
        int idx = ridx[b * HH + t];
        tau[t] = softplusf(tauk[t * NRATES + idx]);
    }
    __syncthreads();
    if (t < NM * SA) {
        int m = t / SA, s = t % SA;
        int h = m / KK;
        w[m][s]    = expf(tau[h] * g_lam[m][s]);
        sps[m][s]  = g_sp[m][s];
        isps[m][s] = g_isp[m][s];
    }
    __syncthreads();
    for (int e = t; e < NM * SA * SA; e += blockDim.x) {
        int m = e / (SA * SA);
        int rs = e % (SA * SA);
        int j = rs / SA, s = rs % SA;
        float uu = g_U[m][j][s];
        Us[m][j][s] = uu;
        Vs[m][j][s] = uu * w[m][s];
    }
    __syncthreads();
    for (int e = t; e < NM * SA * SA; e += blockDim.x) {
        int m = e / (SA * SA);
        int rs = e % (SA * SA);
        int i = rs / SA, j = rs % SA;
        float acc = 0.f;
#pragma unroll
        for (int s = 0; s < SA; s++) acc += Us[m][i][s] * Vs[m][j][s];
        Pm[m * SA * SA + i * SA + j] = isps[m][i] * acc * sps[m][j];
    }
    __syncthreads();

    // coalesced write stream: block span = PPB2*40 floats = 5120 float4s
    float4* op = (float4*)(out + (size_t)posbase * (KK * SA));
    int gp = t / 10;            // position-local of float4 index g = t
    int ge = t - 10 * gp;       // element 0..9 within position
    for (int it = 0; it < 20; it++) {
        int z = zsh[gp];
        int h = gp & 1;                       // posbase even -> parity preserved
        int k = (ge >= 5) ? 1 : 0;
        int off = (h * KK + k) * (SA * SA) + z * SA + (ge - 5 * k) * 4;
        float4 v = *(const float4*)&Pm[off];
        op[t + it * 256] = v;
        // advance g by 256 = 25*10 + 6
        gp += 25; ge += 6; if (ge >= 10) { ge -= 10; gp += 1; }
    }
}

extern "C" void kernel_launch(void* const* d_in, const int* in_sizes, int n_in,
                              void* d_out, int out_size) {
    const float* inputs = (const float*)d_in[0];   // (B,L,H,20) f32
    const int*   ridx   = (const int*)d_in[1];     // (B,H) i32
    const float* tauk   = (const float*)d_in[2];   // (H,NUM_RATES) f32
    const float* exch   = (const float*)d_in[3];   // (H,K,20,20) f32
    const float* equil  = (const float*)d_in[4];   // (H,K,20) f32
    float* out = (float*)d_out;                    // (B,L,H,K,20) f32

    eig_scan_kernel<<<NM + SCANB, 512>>>(exch, equil, inputs);
    anc_kernel<<<BB * BPB2, 256>>>(ridx, tauk, out);
}

// round 15
// speedup vs baseline: 1.2061x; 1.0087x over previous
#include <cuda_runtime.h>
#include <cstdint>

#define SA 20        // alphabet
#define HH 2
#define KK 2
#define NM 4         // H*K matrices
#define LL 512
#define BB 1024
#define NRATES 100000
#define NSWEEP 5
#define NPOS (BB * LL * HH)      // 1,048,576 positions
#define SCANB 2048               // scan blocks (512 pos each)
#define PPB2 512                 // positions per anc block
#define BPB2 2                   // anc blocks per batch item

// persistent scratch (allocation-free rule: __device__ globals)
__device__ float   g_U[NM][SA][SA];
__device__ float   g_lam[NM][SA];
__device__ float   g_sp[NM][SA];
__device__ float   g_isp[NM][SA];
__device__ unsigned char g_z[NPOS];   // argmax index per position

__device__ __forceinline__ float softplusf(float x) {
    return fmaxf(x, 0.f) + log1pf(expf(-fabsf(x)));
}

// ---------------- Kernel 1: eig (blocks 0..NM-1) + ballot scan (rest) ----------------
__global__ __launch_bounds__(512, 2)
void eig_scan_kernel(const float* __restrict__ exch, const float* __restrict__ equil,
                     const float* __restrict__ inputs) {
    const int t = threadIdx.x;

    if (blockIdx.x >= NM) {
        // ========== ballot scan: one-hot -> z table ==========
        // 16 warps; per round a warp covers 8 positions = 160 elements via 5 ballots.
        // 4 rounds -> 512 positions per block.
        __shared__ unsigned int masks[16][8];   // 5 masks + pad (word+1 access safe)
        __shared__ unsigned char zsh[512];
        const int sb = blockIdx.x - NM;
        const int posbase = sb * 512;
        const int w = t >> 5;
        const int lane = t & 31;
        const float* ibase = inputs + (size_t)posbase * SA;

#pragma unroll
        for (int r = 0; r < 4; r++) {
            int relpos = (r * 16 + w) * 8;          // first of 8 positions this warp/round
            const float* ep = ibase + relpos * SA;  // 160 consecutive elements
#pragma unroll
            for (int k = 0; k < 5; k++) {
                float v = ep[k * 32 + lane];
                unsigned int mk = __ballot_sync(0xffffffffu, v > 0.5f);
                if (lane == k) masks[w][k] = mk;    // lane k stores mask k
            }
            if (lane == 5) masks[w][5] = 0u;        // pad for word+1
            __syncwarp();
            if (lane < 8) {
                int bitpos = 20 * lane;
                int word = bitpos >> 5;
                int sh = bitpos & 31;
                unsigned int bits = __funnelshift_r(masks[w][word], masks[w][word + 1], sh) & 0xFFFFFu;
                zsh[relpos + lane] = (unsigned char)(__ffs(bits) - 1);
            }
            __syncwarp();
        }
        __syncthreads();
        if (t < 128) {   // pack: coalesced 512B store
            unsigned int wz = (unsigned int)zsh[4 * t]
                            | ((unsigned int)zsh[4 * t + 1] << 8)
                            | ((unsigned int)zsh[4 * t + 2] << 16)
                            | ((unsigned int)zsh[4 * t + 3] << 24);
            ((unsigned int*)(g_z + posbase))[t] = wz;
        }
        return;
    }

    // ========== eig path: one barrier/round, replicated fast pivots (R11-validated) ==========
    __shared__ float Abuf[2][SA][SA + 1];
    __shared__ float Ubuf[2][SA][SA + 1];
    __shared__ int   part[SA - 1][SA];
    __shared__ float pvec[SA], spv[SA], ispv[SA], rowv[SA];
    __shared__ float inv_mue;

    const int m = blockIdx.x;
    const int i = t / SA, j = t % SA;
    const bool act = (t < SA * SA);

    if (t < (SA - 1) * SA) {
        int r = t / SA, idx = t % SA;
        int p;
        if (idx == 0) {
            p = 1 + (18 + r) % 19;
        } else {
            int s = 1 + ((idx - 1 - r) % 19 + 19) % 19;
            int ps = 19 - s;
            p = (ps == 0) ? 0 : 1 + (ps - 1 + r) % 19;
        }
        part[r][idx] = p;
    }

    if (t == 0) {
        float mx = -1e30f;
        for (int s = 0; s < SA; s++) mx = fmaxf(mx, equil[m * SA + s]);
        float e[SA], sum = 0.f;
        for (int s = 0; s < SA; s++) { e[s] = expf(equil[m * SA + s] - mx); sum += e[s]; }
        float inv = 1.f / sum;
        for (int s = 0; s < SA; s++) {
            float ps = e[s] * inv;
            pvec[s] = ps;
            float sq = sqrtf(ps);
            spv[s] = sq;
            ispv[s] = 1.f / sq;
        }
    }
    __syncthreads();

    if (act) {
        float kij = exch[m * SA * SA + i * SA + j];
        float kji = exch[m * SA * SA + j * SA + i];
        float rr = (i == j) ? 0.f : softplusf(0.5f * (kij + kji));
        Abuf[0][i][j] = rr * pvec[j];
    }
    __syncthreads();
    if (t < SA) { float s = 0.f; for (int jj = 0; jj < SA; jj++) s += Abuf[0][t][jj]; rowv[t] = s; }
    __syncthreads();
    if (t == 0) {
        float mue = 0.f;
        for (int ii = 0; ii < SA; ii++) mue += pvec[ii] * rowv[ii];
        inv_mue = 1.f / fmaxf(mue, 1e-16f);
    }
    __syncthreads();
    if (act) {
        float q = (Abuf[0][i][j] - ((i == j) ? rowv[i] : 0.f)) * inv_mue;
        Abuf[1][i][j] = spv[i] * q * ispv[j];
    }
    __syncthreads();

    float a = 0.f, u = 0.f;
    if (act) {
        a = 0.5f * (Abuf[1][i][j] + Abuf[1][j][i]);
        u = (i == j) ? 1.f : 0.f;
    }

    for (int round = 0; round < NSWEEP * (SA - 1); round++) {
        const int p = round & 1;
        const int r = round % (SA - 1);
        if (act) { Abuf[p][i][j] = a; Ubuf[p][i][j] = u; }
        __syncthreads();
        if (act) {
            const int pi = part[r][i], pj = part[r][j];
            float aii = Abuf[p][i][i], app_i = Abuf[p][pi][pi], aipi = Abuf[p][i][pi];
            float ci = 1.f, si = 0.f;
            if (fabsf(aipi) > 1e-13f) {
                float th = __fdividef(app_i - aii, 2.f * aipi);
                float t2 = th * th + 1.f;
                float den = fabsf(th) + t2 * rsqrtf(t2);
                float tt = __fdividef(copysignf(1.f, th), den);
                ci = rsqrtf(tt * tt + 1.f);
                si = -tt * ci;
            }
            float ajj = Abuf[p][j][j], app_j = Abuf[p][pj][pj], ajpj = Abuf[p][j][pj];
            float cj = 1.f, sj = 0.f;
            if (fabsf(ajpj) > 1e-13f) {
                float th = __fdividef(app_j - ajj, 2.f * ajpj);
                float t2 = th * th + 1.f;
                float den = fabsf(th) + t2 * rsqrtf(t2);
                float tt = __fdividef(copysignf(1.f, th), den);
                cj = rsqrtf(tt * tt + 1.f);
                sj = -tt * cj;
            }
            float a01 = Abuf[p][i][pj];
            float a10 = Abuf[p][pi][j];
            float a11 = Abuf[p][pi][pj];
            float u1  = Ubuf[p][i][pj];
            a = ci * (cj * a + sj * a01) + si * (cj * a10 + sj * a11);
            u = cj * u + sj * u1;
        }
    }

    if (act) {
        g_U[m][i][j] = u;
        if (i == j) g_lam[m][i] = a;
    }
    if (t < SA) {
        g_sp[m][t]  = spv[t];
        g_isp[m][t] = ispv[t];
    }
}

// ---------------- Kernel 2: P reconstruction + pure coalesced write stream ----------------
__global__ __launch_bounds__(256, 8)
void anc_kernel(const int* __restrict__ ridx, const float* __restrict__ tauk,
                float* __restrict__ out) {
    __shared__ __align__(16) float Pm[NM * SA * SA];   // [(h*KK+k)*400 + z*20 + s]
    __shared__ __align__(16) float Us[NM][SA][SA];
    __shared__ __align__(16) float Vs[NM][SA][SA];
    __shared__ float w[NM][SA];
    __shared__ float sps[NM][SA], isps[NM][SA];
    __shared__ float tau[HH];
    __shared__ int   zsh[PPB2];

    const int b = blockIdx.x >> 1;        // BPB2 = 2
    const int q = blockIdx.x & 1;
    const int t = threadIdx.x;
    const int posbase = b * (LL * HH) + q * PPB2;

    if (t < PPB2 / 4) {
        unsigned int wz = ((const unsigned int*)(g_z + posbase))[t];
        zsh[4 * t]     = wz & 0xff;
        zsh[4 * t + 1] = (wz >> 8) & 0xff;
        zsh[4 * t + 2] = (wz >> 16) & 0xff;
        zsh[4 * t + 3] = (wz >> 24) & 0xff;
    }
    if (t < HH) {
        int idx = ridx[b * HH + t];
        tau[t] = softplusf(tauk[t * NRATES + idx]);
    }
    __syncthreads();
    if (t < NM * SA) {
        int m = t / SA, s = t % SA;
        int h = m / KK;
        w[m][s]    = expf(tau[h] * g_lam[m][s]);
        sps[m][s]  = g_sp[m][s];
        isps[m][s] = g_isp[m][s];
    }
    __syncthreads();
    for (int e = t; e < NM * SA * SA; e += blockDim.x) {
        int m = e / (SA * SA);
        int rs = e % (SA * SA);
        int j = rs / SA, s = rs % SA;
        float uu = g_U[m][j][s];
        Us[m][j][s] = uu;
        Vs[m][j][s] = uu * w[m][s];
    }
    __syncthreads();
    for (int e = t; e < NM * SA * SA; e += blockDim.x) {
        int m = e / (SA * SA);
        int rs = e % (SA * SA);
        int i = rs / SA, j = rs % SA;
        float acc = 0.f;
#pragma unroll
        for (int s = 0; s < SA; s++) acc += Us[m][i][s] * Vs[m][j][s];
        Pm[m * SA * SA + i * SA + j] = isps[m][i] * acc * sps[m][j];
    }
    __syncthreads();

    // coalesced write stream: block span = PPB2*40 floats = 5120 float4s
    float4* op = (float4*)(out + (size_t)posbase * (KK * SA));
    int gp = t / 10;            // position-local of float4 index g = t
    int ge = t - 10 * gp;       // element 0..9 within position
    for (int it = 0; it < 20; it++) {
        int z = zsh[gp];
        int h = gp & 1;
        int k = (ge >= 5) ? 1 : 0;
        int off = (h * KK + k) * (SA * SA) + z * SA + (ge - 5 * k) * 4;
        float4 v = *(const float4*)&Pm[off];
        op[t + it * 256] = v;
        gp += 25; ge += 6; if (ge >= 10) { ge -= 10; gp += 1; }
    }
}

extern "C" void kernel_launch(void* const* d_in, const int* in_sizes, int n_in,
                              void* d_out, int out_size) {
    const float* inputs = (const float*)d_in[0];   // (B,L,H,20) f32
    const int*   ridx   = (const int*)d_in[1];     // (B,H) i32
    const float* tauk   = (const float*)d_in[2];   // (H,NUM_RATES) f32
    const float* exch   = (const float*)d_in[3];   // (H,K,20,20) f32
    const float* equil  = (const float*)d_in[4];   // (H,K,20) f32
    float* out = (float*)d_out;                    // (B,L,H,K,20) f32

    eig_scan_kernel<<<NM + SCANB, 512>>>(exch, equil, inputs);
    anc_kernel<<<BB * BPB2, 256>>>(ridx, tauk, out);
}

// round 16
// speedup vs baseline: 1.7051x; 1.4137x over previous
#include <cuda_runtime.h>
#include <cstdint>

#define SA 20        // alphabet
#define HH 2
#define KK 2
#define NM 4         // H*K matrices
#define LL 512
#define BB 1024
#define NRATES 100000
#define NPOW 7       // I, Q^1..Q^6 (slot 0 unused)
#define PPB 512      // positions per anc block
#define NBLK (BB * LL * HH / PPB)   // 2048 anc blocks

// persistent scratch (allocation-free rule: __device__ globals)
__device__ float g_Qpow[NM][NPOW][SA * SA];

__device__ __forceinline__ float softplusf(float x) {
    return fmaxf(x, 0.f) + log1pf(expf(-fabsf(x)));
}

// ---------------- Kernel S: build Q per (h,k) and powers Q^2..Q^6 ----------------
__global__ __launch_bounds__(256, 1)
void qpow_kernel(const float* __restrict__ exch, const float* __restrict__ equil) {
    __shared__ float Q[SA * SA];
    __shared__ float A[SA * SA];
    __shared__ float Bm[SA * SA];
    __shared__ float pvec[SA], rowv[SA];
    __shared__ float inv_mue;

    const int m = blockIdx.x;
    const int t = threadIdx.x;

    if (t == 0) {
        float mx = -1e30f;
        for (int s = 0; s < SA; s++) mx = fmaxf(mx, equil[m * SA + s]);
        float e[SA], sum = 0.f;
        for (int s = 0; s < SA; s++) { e[s] = expf(equil[m * SA + s] - mx); sum += e[s]; }
        float inv = 1.f / sum;
        for (int s = 0; s < SA; s++) pvec[s] = e[s] * inv;
    }
    __syncthreads();

    // pre-diagonal Q0 = softplus(0.5(Kij+Kji)) * (i!=j) * p_j
    for (int e = t; e < SA * SA; e += 256) {
        int i = e / SA, j = e % SA;
        float kij = exch[m * SA * SA + i * SA + j];
        float kji = exch[m * SA * SA + j * SA + i];
        float r = (i == j) ? 0.f : softplusf(0.5f * (kij + kji));
        Q[e] = r * pvec[j];
    }
    __syncthreads();
    if (t < SA) { float s = 0.f; for (int j = 0; j < SA; j++) s += Q[t * SA + j]; rowv[t] = s; }
    __syncthreads();
    if (t == 0) {
        float mue = 0.f;
        for (int i = 0; i < SA; i++) mue += pvec[i] * rowv[i];
        inv_mue = 1.f / fmaxf(mue, 1e-16f);
    }
    __syncthreads();
    for (int e = t; e < SA * SA; e += 256) {
        int i = e / SA, j = e % SA;
        Q[e] = (Q[e] - ((i == j) ? rowv[i] : 0.f)) * inv_mue;
    }
    __syncthreads();
    for (int e = t; e < SA * SA; e += 256) {
        g_Qpow[m][1][e] = Q[e];
        A[e] = Q[e];
    }
    __syncthreads();

    for (int n = 2; n <= 6; n++) {
        for (int e = t; e < SA * SA; e += 256) {
            int i = e / SA, j = e % SA;
            float acc = 0.f;
#pragma unroll
            for (int s = 0; s < SA; s++) acc += A[i * SA + s] * Q[s * SA + j];
            Bm[e] = acc;
        }
        __syncthreads();
        for (int e = t; e < SA * SA; e += 256) {
            A[e] = Bm[e];
            g_Qpow[m][n][e] = Bm[e];
        }
        __syncthreads();
    }
}

// ---------------- Kernel A: fused ballot scan + Taylor P build + coalesced write ----------------
// 256 threads (8 warps), 512 positions per block.
__global__ __launch_bounds__(256, 8)
void anc_kernel(const float* __restrict__ inputs, const int* __restrict__ ridx,
                const float* __restrict__ tauk, float* __restrict__ out) {
    __shared__ __align__(16) float Pm[NM * SA * SA];   // [(h*KK+k)*400 + z*20 + s]
    __shared__ unsigned int masks[8][8];               // 5 masks + pad per warp
    __shared__ unsigned char zsh[PPB];
    __shared__ float tau[HH];

    const int blk = blockIdx.x;
    const int b = blk >> 1;                 // 2 blocks per batch item
    const int t = threadIdx.x;
    const int w = t >> 5;
    const int lane = t & 31;
    const int posbase = blk * PPB;

    if (t < HH) {
        int idx = ridx[b * HH + t];
        tau[t] = softplusf(tauk[t * NRATES + idx]);
    }

    // ---- Phase A: ballot scan of own 512 positions ----
    // 8 warps; per round a warp covers 8 positions = 160 elements via 5 ballots.
    const float* ibase = inputs + (size_t)posbase * SA;
#pragma unroll
    for (int r = 0; r < 8; r++) {
        int relpos = (r * 8 + w) * 8;           // first of 8 positions this warp/round
        const float* ep = ibase + relpos * SA;  // 160 consecutive elements
#pragma unroll
        for (int k = 0; k < 5; k++) {
            float v = ep[k * 32 + lane];
            unsigned int mk = __ballot_sync(0xffffffffu, v > 0.5f);
            if (lane == k) masks[w][k] = mk;
        }
        if (lane == 5) masks[w][5] = 0u;        // pad for word+1
        __syncwarp();
        if (lane < 8) {
            int bitpos = 20 * lane;
            int word = bitpos >> 5;
            int sh = bitpos & 31;
            unsigned int bits = __funnelshift_r(masks[w][word], masks[w][word + 1], sh) & 0xFFFFFu;
            zsh[relpos + lane] = (unsigned char)(__ffs(bits) - 1);
        }
        __syncwarp();
    }
    __syncthreads();   // tau + (warps' own zsh regions complete; full visibility next barrier)

    // ---- Phase B: P = I + tau(Q1 + tau/2(Q2 + tau/3(Q3 + tau/4(Q4 + tau/5(Q5 + tau/6 Q6)))))
    for (int e = t; e < NM * SA * SA; e += 256) {
        int m = e / (SA * SA);
        int rs = e - m * (SA * SA);
        int i = rs / SA, j = rs - i * SA;
        float th = tau[m >> 1];                 // m = h*KK + k
        const float* qp = &g_Qpow[m][0][rs];
        float q1 = qp[1 * SA * SA];
        float q2 = qp[2 * SA * SA];
        float q3 = qp[3 * SA * SA];
        float q4 = qp[4 * SA * SA];
        float q5 = qp[5 * SA * SA];
        float q6 = qp[6 * SA * SA];
        float v = q5 + (th * (1.f / 6.f)) * q6;
        v = q4 + (th * (1.f / 5.f)) * v;
        v = q3 + (th * (1.f / 4.f)) * v;
        v = q2 + (th * (1.f / 3.f)) * v;
        v = q1 + (th * (1.f / 2.f)) * v;
        Pm[e] = ((i == j) ? 1.f : 0.f) + th * v;
    }
    __syncthreads();

    // ---- Phase C: coalesced write stream (PPB*40 floats = 5120 float4s) ----
    float4* op = (float4*)(out + (size_t)posbase * (KK * SA));
    int gp = t / 10;            // position-local of float4 index g = t
    int ge = t - 10 * gp;       // element 0..9 within position
    for (int it = 0; it < 20; it++) {
        int z = zsh[gp];
        int h = gp & 1;                        // posbase multiple of 512 -> parity kept
        int k = (ge >= 5) ? 1 : 0;
        int off = (h * KK + k) * (SA * SA) + z * SA + (ge - 5 * k) * 4;
        float4 v = *(const float4*)&Pm[off];
        op[t + it * 256] = v;
        // advance g by 256 = 25*10 + 6
        gp += 25; ge += 6; if (ge >= 10) { ge -= 10; gp += 1; }
    }
}

extern "C" void kernel_launch(void* const* d_in, const int* in_sizes, int n_in,
                              void* d_out, int out_size) {
    const float* inputs = (const float*)d_in[0];   // (B,L,H,20) f32
    const int*   ridx   = (const int*)d_in[1];     // (B,H) i32
    const float* tauk   = (const float*)d_in[2];   // (H,NUM_RATES) f32
    const float* exch   = (const float*)d_in[3];   // (H,K,20,20) f32
    const float* equil  = (const float*)d_in[4];   // (H,K,20) f32
    float* out = (float*)d_out;                    // (B,L,H,K,20) f32

    qpow_kernel<<<NM, 256>>>(exch, equil);
    anc_kernel<<<NBLK, 256>>>(inputs, ridx, tauk, out);
}